// round 16
// baseline (speedup 1.0000x reference)
#include <cuda_runtime.h>
#include <cuda_bf16.h>
#include <cstdint>
#include <cstddef>

#define NMAX 50000
#define NEG_BIG (-1.0e30f)

__device__ float g_qk[(size_t)NMAX * 512];   // [n][h*128+j]
__device__ float g_agg[(size_t)NMAX * 512];  // [n][h*128+j]
__device__ int   g_rs[NMAX + 1];
__device__ __nv_bfloat16 g_M1hi[512 * 128], g_M1lo[512 * 128];  // [o][k]
__device__ __nv_bfloat16 g_M2hi[128 * 512], g_M2lo[128 * 512];  // [o][kk]

typedef unsigned long long ull;
__device__ __forceinline__ void f2_fma(ull& a, ull b, ull c) {
    asm("fma.rn.f32x2 %0, %1, %2, %0;" : "+l"(a) : "l"(b), "l"(c));
}
__device__ __forceinline__ float f2_sum(ull v) {
    float x, y; asm("mov.b64 {%0,%1}, %2;" : "=f"(x), "=f"(y) : "l"(v)); return x + y;
}

__device__ __forceinline__ void mma_bf16(float* c, const uint32_t* a, const uint32_t* b) {
    asm volatile(
        "mma.sync.aligned.m16n8k16.row.col.f32.bf16.bf16.f32 "
        "{%0,%1,%2,%3}, {%4,%5,%6,%7}, {%8,%9}, {%0,%1,%2,%3};"
        : "+f"(c[0]), "+f"(c[1]), "+f"(c[2]), "+f"(c[3])
        : "r"(a[0]), "r"(a[1]), "r"(a[2]), "r"(a[3]), "r"(b[0]), "r"(b[1]));
}

// ---- segment bounds ----
__global__ void k_init_rs(int N, int E) {
    int t = blockIdx.x * blockDim.x + threadIdx.x;
    if (t <= N) g_rs[t] = E;
}
__global__ void k_bounds(const int* __restrict__ center, int E) {
    int e = blockIdx.x * blockDim.x + threadIdx.x;
    if (e >= E) return;
    int c = center[e];
    int p = (e == 0) ? -1 : center[e - 1];
    for (int n = p + 1; n <= c; n++) g_rs[n] = e;
}

// ---- combined weights (bf16 hi/lo) ----
__global__ void k_m1(const float* __restrict__ WQ, const float* __restrict__ WK) {
    int k = blockIdx.x, o = threadIdx.x, h = o >> 7, j = o & 127;
    float s = 0.f;
#pragma unroll 8
    for (int d = 0; d < 32; d++)
        s += WQ[(size_t)(h * 32 + d) * 128 + k] * WK[(size_t)(h * 32 + d) * 128 + j];
    s *= 0.17677669529663687f;
    __nv_bfloat16 hi = __float2bfloat16(s);
    g_M1hi[o * 128 + k] = hi;
    g_M1lo[o * 128 + k] = __float2bfloat16(s - __bfloat162float(hi));
}
__global__ void k_m2(const float* __restrict__ WO, const float* __restrict__ WV) {
    int o = blockIdx.x, kk = threadIdx.x, h = kk >> 7, j = kk & 127;
    float s = 0.f;
#pragma unroll 8
    for (int d = 0; d < 32; d++)
        s += WO[(size_t)o * 128 + h * 32 + d] * WV[(size_t)(h * 32 + d) * 128 + j];
    __nv_bfloat16 hi = __float2bfloat16(s);
    g_M2hi[o * 512 + kk] = hi;
    g_M2lo[o * 512 + kk] = __float2bfloat16(s - __bfloat162float(hi));
}

#define PAD 136
#define SMEM_GEMM ((2 * 128 + 2 * 64) * PAD * 2)

__device__ __forceinline__ void store_hl(__nv_bfloat16* Ah, __nv_bfloat16* Al,
                                         int off, float2 v) {
    __nv_bfloat16 hx = __float2bfloat16(v.x), hy = __float2bfloat16(v.y);
    *(__nv_bfloat162*)(Ah + off) = __halves2bfloat162(hx, hy);
    __nv_bfloat16 lx = __float2bfloat16(v.x - __bfloat162float(hx));
    __nv_bfloat16 ly = __float2bfloat16(v.y - __bfloat162float(hy));
    *(__nv_bfloat162*)(Al + off) = __halves2bfloat162(lx, ly);
}

// ---- qk = hV @ M1  (M tile 128, N=512 in 8 chunks of 64, K=128) ----
__global__ __launch_bounds__(512, 2) void k_gemm_qk(const float* __restrict__ X, int N) {
    extern __shared__ char sm[];
    __nv_bfloat16* Ah = (__nv_bfloat16*)sm;
    __nv_bfloat16* Al = Ah + 128 * PAD;
    __nv_bfloat16* Bh = Al + 128 * PAD;
    __nv_bfloat16* Bl = Bh + 64 * PAD;
    int t = threadIdx.x, lane = t & 31, wid = t >> 5;
    int wr = wid >> 1, wc = wid & 1, g = lane >> 2, tig = lane & 3;
    int n0 = blockIdx.x * 128;

    for (int idx = t; idx < 128 * 64; idx += 512) {
        int r = idx >> 6, kp = (idx & 63) * 2;
        float2 v = (n0 + r < N) ? *(const float2*)(X + (size_t)(n0 + r) * 128 + kp)
                                : make_float2(0.f, 0.f);
        store_hl(Ah, Al, r * PAD + kp, v);
    }
    int ra = 16 * wr + g;
    for (int nc = 0; nc < 8; nc++) {
        if (nc) __syncthreads();
        for (int idx = t; idx < 64 * 16; idx += 512) {
            int r = idx >> 4, k8 = (idx & 15) * 8;
            *(uint4*)(Bh + r * PAD + k8) = *(const uint4*)(g_M1hi + (size_t)(nc * 64 + r) * 128 + k8);
            *(uint4*)(Bl + r * PAD + k8) = *(const uint4*)(g_M1lo + (size_t)(nc * 64 + r) * 128 + k8);
        }
        __syncthreads();
        float acc[4][4];
#pragma unroll
        for (int nt = 0; nt < 4; nt++)
#pragma unroll
            for (int c = 0; c < 4; c++) acc[nt][c] = 0.f;
#pragma unroll
        for (int ks = 0; ks < 8; ks++) {
            int k0 = 16 * ks + tig * 2;
            uint32_t ah[4], al[4];
            ah[0] = *(const uint32_t*)(Ah + ra * PAD + k0);
            ah[1] = *(const uint32_t*)(Ah + (ra + 8) * PAD + k0);
            ah[2] = *(const uint32_t*)(Ah + ra * PAD + k0 + 8);
            ah[3] = *(const uint32_t*)(Ah + (ra + 8) * PAD + k0 + 8);
            al[0] = *(const uint32_t*)(Al + ra * PAD + k0);
            al[1] = *(const uint32_t*)(Al + (ra + 8) * PAD + k0);
            al[2] = *(const uint32_t*)(Al + ra * PAD + k0 + 8);
            al[3] = *(const uint32_t*)(Al + (ra + 8) * PAD + k0 + 8);
#pragma unroll
            for (int nt = 0; nt < 4; nt++) {
                int nb = 32 * wc + 8 * nt + g;
                uint32_t bh[2], bl[2];
                bh[0] = *(const uint32_t*)(Bh + nb * PAD + k0);
                bh[1] = *(const uint32_t*)(Bh + nb * PAD + k0 + 8);
                bl[0] = *(const uint32_t*)(Bl + nb * PAD + k0);
                bl[1] = *(const uint32_t*)(Bl + nb * PAD + k0 + 8);
                mma_bf16(acc[nt], ah, bh);
                mma_bf16(acc[nt], ah, bl);
                mma_bf16(acc[nt], al, bh);
            }
        }
        int r0 = n0 + ra;
#pragma unroll
        for (int nt = 0; nt < 4; nt++) {
            int col = nc * 64 + 32 * wc + 8 * nt + tig * 2;
            if (r0 < N)
                *(float2*)(g_qk + (size_t)r0 * 512 + col) = make_float2(acc[nt][0], acc[nt][1]);
            if (r0 + 8 < N)
                *(float2*)(g_qk + (size_t)(r0 + 8) * 512 + col) = make_float2(acc[nt][2], acc[nt][3]);
        }
    }
}

// ---- out = agg @ M2  (M tile 128, N=128, K=512 in 4 chunks; B in 2 sub-chunks) ----
__global__ __launch_bounds__(512, 2) void k_gemm_out(float* __restrict__ OUT, int N) {
    extern __shared__ char sm[];
    __nv_bfloat16* Ah = (__nv_bfloat16*)sm;
    __nv_bfloat16* Al = Ah + 128 * PAD;
    __nv_bfloat16* Bh = Al + 128 * PAD;
    __nv_bfloat16* Bl = Bh + 64 * PAD;
    int t = threadIdx.x, lane = t & 31, wid = t >> 5;
    int wr = wid >> 1, wc = wid & 1, g = lane >> 2, tig = lane & 3;
    int n0 = blockIdx.x * 128;
    int ra = 16 * wr + g;

    float acc[8][4];
#pragma unroll
    for (int a = 0; a < 8; a++)
#pragma unroll
        for (int c = 0; c < 4; c++) acc[a][c] = 0.f;

    for (int kc = 0; kc < 4; kc++) {
        if (kc) __syncthreads();
        for (int idx = t; idx < 128 * 64; idx += 512) {
            int r = idx >> 6, kp = (idx & 63) * 2;
            float2 v = (n0 + r < N)
                ? *(const float2*)(g_agg + (size_t)(n0 + r) * 512 + kc * 128 + kp)
                : make_float2(0.f, 0.f);
            store_hl(Ah, Al, r * PAD + kp, v);
        }
        for (int sub = 0; sub < 2; sub++) {
            if (sub) __syncthreads();
            for (int idx = t; idx < 64 * 16; idx += 512) {
                int r = idx >> 4, k8 = (idx & 15) * 8;
                *(uint4*)(Bh + r * PAD + k8) =
                    *(const uint4*)(g_M2hi + (size_t)(sub * 64 + r) * 512 + kc * 128 + k8);
                *(uint4*)(Bl + r * PAD + k8) =
                    *(const uint4*)(g_M2lo + (size_t)(sub * 64 + r) * 512 + kc * 128 + k8);
            }
            __syncthreads();
#pragma unroll
            for (int ks = 0; ks < 8; ks++) {
                int k0 = 16 * ks + tig * 2;
                uint32_t ah[4], al[4];
                ah[0] = *(const uint32_t*)(Ah + ra * PAD + k0);
                ah[1] = *(const uint32_t*)(Ah + (ra + 8) * PAD + k0);
                ah[2] = *(const uint32_t*)(Ah + ra * PAD + k0 + 8);
                ah[3] = *(const uint32_t*)(Ah + (ra + 8) * PAD + k0 + 8);
                al[0] = *(const uint32_t*)(Al + ra * PAD + k0);
                al[1] = *(const uint32_t*)(Al + (ra + 8) * PAD + k0);
                al[2] = *(const uint32_t*)(Al + ra * PAD + k0 + 8);
                al[3] = *(const uint32_t*)(Al + (ra + 8) * PAD + k0 + 8);
#pragma unroll
                for (int nt = 0; nt < 4; nt++) {
                    int nb = 32 * wc + 8 * nt + g;
                    uint32_t bh[2], bl[2];
                    bh[0] = *(const uint32_t*)(Bh + nb * PAD + k0);
                    bh[1] = *(const uint32_t*)(Bh + nb * PAD + k0 + 8);
                    bl[0] = *(const uint32_t*)(Bl + nb * PAD + k0);
                    bl[1] = *(const uint32_t*)(Bl + nb * PAD + k0 + 8);
                    mma_bf16(acc[sub * 4 + nt], ah, bh);
                    mma_bf16(acc[sub * 4 + nt], ah, bl);
                    mma_bf16(acc[sub * 4 + nt], al, bh);
                }
            }
        }
    }
    int r0 = n0 + ra;
#pragma unroll
    for (int a = 0; a < 8; a++) {
        int col = (a >> 2) * 64 + 32 * wc + 8 * (a & 3) + tig * 2;
        if (r0 < N)
            *(float2*)(OUT + (size_t)r0 * 128 + col) = make_float2(acc[a][0], acc[a][1]);
        if (r0 + 8 < N)
            *(float2*)(OUT + (size_t)(r0 + 8) * 128 + col) = make_float2(acc[a][2], acc[a][3]);
    }
}

// ---- per-node single pass over h_E: SMEM online softmax + aggregation ----
// Accumulate: column ownership (thread t<128 owns column t, all 4 heads at once).
#define CH 40
#define PADR 132
__global__ __launch_bounds__(256) void k_node(const float* __restrict__ hE, int N) {
    __shared__ alignas(16) float hE_s[CH * PADR];
    __shared__ alignas(16) float qk_s[4 * PADR];
    __shared__ alignas(16) float lgT[4 * 68];
    __shared__ alignas(16) float pQ[CH * 4];   // transposed: p[e][h]
    __shared__ float m_s[4], s_s[4], sc_s[4];
    int t = threadIdx.x;
    int n = blockIdx.x;
    if (n >= N) return;
    int beg = g_rs[n], end = g_rs[n + 1];
    int w = t >> 5, l = t & 31;

    if (end - beg <= CH) {
        // ---------- fast path ----------
        int cnt = end - beg;
        for (int idx = t; idx < 512; idx += 256) {
            int hh = idx >> 7, j = idx & 127;
            qk_s[hh * PADR + j] = g_qk[(size_t)n * 512 + idx];
        }
        for (int idx = t; idx < cnt * 32; idx += 256) {
            int r = idx >> 5, c4 = idx & 31;
            float4 v = *(const float4*)(hE + (size_t)(beg + r) * 128 + c4 * 4);
            *(float4*)(&hE_s[r * PADR + c4 * 4]) = v;
        }
        __syncthreads();
        {   // logits
            int e = t >> 2, hq = t & 3;
            if (e < cnt) {
                ull a0 = 0ull, a1 = 0ull;
                const float* qp = &qk_s[hq * PADR];
                const float* xp = &hE_s[e * PADR];
#pragma unroll
                for (int jj = 0; jj < 32; jj++) {
                    ulonglong2 q4 = *(const ulonglong2*)(qp + jj * 4);
                    ulonglong2 x4 = *(const ulonglong2*)(xp + jj * 4);
                    f2_fma(a0, q4.x, x4.x);
                    f2_fma(a1, q4.y, x4.y);
                }
                lgT[hq * 68 + e] = f2_sum(a0) + f2_sum(a1);
            }
        }
        __syncthreads();
        if (w < 4) {  // fused max + exp + sum (head w), write transposed pQ
            float v1 = (l < cnt) ? lgT[w * 68 + l] : NEG_BIG;
            float v2 = (l + 32 < cnt) ? lgT[w * 68 + l + 32] : NEG_BIG;
            float mx = fmaxf(v1, v2);
#pragma unroll
            for (int o = 16; o; o >>= 1) mx = fmaxf(mx, __shfl_xor_sync(0xffffffffu, mx, o));
            float p1 = (l < cnt) ? __expf(v1 - mx) : 0.f;
            float p2 = (l + 32 < cnt) ? __expf(v2 - mx) : 0.f;
            pQ[l * 4 + w] = p1;
            if (l + 32 < CH) pQ[(l + 32) * 4 + w] = p2;
            float sv = p1 + p2;
#pragma unroll
            for (int o = 16; o; o >>= 1) sv += __shfl_xor_sync(0xffffffffu, sv, o);
            if (l == 0) s_s[w] = sv;
        }
        __syncthreads();
        if (t < 128) {  // column-ownership accumulate: 1 x-LDS + 1 p-LDS.128 + 4 FMA per edge
            float a0 = 0.f, a1 = 0.f, a2 = 0.f, a3 = 0.f;
#pragma unroll 4
            for (int e = 0; e < cnt; e++) {
                float x = hE_s[e * PADR + t];
                float4 p = *(const float4*)(pQ + e * 4);
                a0 = fmaf(p.x, x, a0); a1 = fmaf(p.y, x, a1);
                a2 = fmaf(p.z, x, a2); a3 = fmaf(p.w, x, a3);
            }
            float i0 = (cnt > 0) ? 1.f / s_s[0] : 0.f;
            float i1 = (cnt > 0) ? 1.f / s_s[1] : 0.f;
            float i2 = (cnt > 0) ? 1.f / s_s[2] : 0.f;
            float i3 = (cnt > 0) ? 1.f / s_s[3] : 0.f;
            float* op = g_agg + (size_t)n * 512 + t;
            op[0] = a0 * i0; op[128] = a1 * i1; op[256] = a2 * i2; op[384] = a3 * i3;
        }
        return;
    }

    // ---------- general path: online softmax over chunks ----------
    for (int idx = t; idx < 512; idx += 256) {
        int hh = idx >> 7, j = idx & 127;
        qk_s[hh * PADR + j] = g_qk[(size_t)n * 512 + idx];
    }
    if (t < 4) { m_s[t] = NEG_BIG; s_s[t] = 0.f; }
    float4 accv = make_float4(0.f, 0.f, 0.f, 0.f);
    __syncthreads();

    for (int cs = beg; cs < end; cs += CH) {
        int cnt = min(CH, end - cs);
        for (int idx = t; idx < cnt * 32; idx += 256) {
            int r = idx >> 5, c4 = idx & 31;
            float4 v = *(const float4*)(hE + (size_t)(cs + r) * 128 + c4 * 4);
            *(float4*)(&hE_s[r * PADR + c4 * 4]) = v;
        }
        __syncthreads();
        {
            int e = t >> 2, hq = t & 3;
            float lg = NEG_BIG;
            if (e < cnt) {
                ull a0 = 0ull, a1 = 0ull;
                const float* qp = &qk_s[hq * PADR];
                const float* xp = &hE_s[e * PADR];
#pragma unroll
                for (int jj = 0; jj < 32; jj++) {
                    ulonglong2 q4 = *(const ulonglong2*)(qp + jj * 4);
                    ulonglong2 x4 = *(const ulonglong2*)(xp + jj * 4);
                    f2_fma(a0, q4.x, x4.x);
                    f2_fma(a1, q4.y, x4.y);
                }
                lg = f2_sum(a0) + f2_sum(a1);
            }
            lgT[hq * 68 + e] = lg;
        }
        __syncthreads();
        if (t < 128) {
            int wh = t >> 5, l2 = t & 31;
            float v = fmaxf(lgT[wh * 68 + l2], lgT[wh * 68 + l2 + 32]);
#pragma unroll
            for (int o = 16; o; o >>= 1) v = fmaxf(v, __shfl_xor_sync(0xffffffffu, v, o));
            if (l2 == 0) {
                float old = m_s[wh], nm = fmaxf(old, v);
                sc_s[wh] = __expf(old - nm);
                m_s[wh] = nm;
            }
        }
        __syncthreads();
        {   // p transposed into pQ
            int e = t >> 2, hq = t & 3;
            if (e < CH) pQ[e * 4 + hq] = (e < cnt) ? __expf(lgT[hq * 68 + e] - m_s[hq]) : 0.f;
        }
        __syncthreads();
        if (t < 128) {  // running sum (head wh)
            int wh = t >> 5, l2 = t & 31;
            float v = pQ[l2 * 4 + wh] + ((l2 + 32 < CH) ? pQ[(l2 + 32) * 4 + wh] : 0.f);
#pragma unroll
            for (int o = 16; o; o >>= 1) v += __shfl_xor_sync(0xffffffffu, v, o);
            if (l2 == 0) s_s[wh] = s_s[wh] * sc_s[wh] + v;
        }
        if (t < 128) {  // column-ownership accumulate with rescale
            accv.x *= sc_s[0]; accv.y *= sc_s[1]; accv.z *= sc_s[2]; accv.w *= sc_s[3];
#pragma unroll 4
            for (int e = 0; e < cnt; e++) {
                float x = hE_s[e * PADR + t];
                float4 p = *(const float4*)(pQ + e * 4);
                accv.x = fmaf(p.x, x, accv.x); accv.y = fmaf(p.y, x, accv.y);
                accv.z = fmaf(p.z, x, accv.z); accv.w = fmaf(p.w, x, accv.w);
            }
        }
        __syncthreads();
    }
    if (t < 128) {
        float i0 = (end > beg) ? 1.f / s_s[0] : 0.f;
        float i1 = (end > beg) ? 1.f / s_s[1] : 0.f;
        float i2 = (end > beg) ? 1.f / s_s[2] : 0.f;
        float i3 = (end > beg) ? 1.f / s_s[3] : 0.f;
        float* op = g_agg + (size_t)n * 512 + t;
        op[0] = accv.x * i0; op[128] = accv.y * i1;
        op[256] = accv.z * i2; op[384] = accv.w * i3;
    }
}

extern "C" void kernel_launch(void* const* d_in, const int* in_sizes, int n_in,
                              void* d_out, int out_size) {
    const float* hV = (const float*)d_in[0];
    const float* hE = (const float*)d_in[1];
    const int* center = (const int*)d_in[2];
    const float* WQ = (const float*)d_in[5];
    const float* WK = (const float*)d_in[6];
    const float* WV = (const float*)d_in[7];
    const float* WO = (const float*)d_in[8];
    float* out = (float*)d_out;
    int N = in_sizes[0] / 128;
    int E = in_sizes[1] / 128;
    int tiles = (N + 127) / 128;

    cudaFuncSetAttribute(k_gemm_qk, cudaFuncAttributeMaxDynamicSharedMemorySize, SMEM_GEMM);
    cudaFuncSetAttribute(k_gemm_out, cudaFuncAttributeMaxDynamicSharedMemorySize, SMEM_GEMM);

    k_init_rs<<<(N + 256) / 256, 256>>>(N, E);
    k_bounds<<<(E + 255) / 256, 256>>>(center, E);
    k_m1<<<128, 512>>>(WQ, WK);
    k_m2<<<128, 512>>>(WO, WV);
    k_gemm_qk<<<tiles, 512, SMEM_GEMM>>>(hV, N);    // qk = hV @ M1 (HMMA, 2 blocks/SM)
    k_node<<<N, 256>>>(hE, N);                      // softmax + aggregate
    k_gemm_out<<<tiles, 512, SMEM_GEMM>>>(out, N);  // out = agg @ M2 (HMMA, 2 blocks/SM)
}

// round 17
// speedup vs baseline: 1.4854x; 1.4854x over previous
#include <cuda_runtime.h>
#include <cuda_bf16.h>
#include <cstdint>
#include <cstddef>

#define NMAX 50000
#define NEG_BIG (-1.0e30f)

__device__ float g_qk[(size_t)NMAX * 512];   // [n][h*128+j]
__device__ float g_agg[(size_t)NMAX * 512];  // [n][h*128+j]
__device__ int   g_rs[NMAX + 1];
__device__ __nv_bfloat16 g_M1hi[512 * 128], g_M1lo[512 * 128];  // [o][k]
__device__ __nv_bfloat16 g_M2hi[128 * 512], g_M2lo[128 * 512];  // [o][kk]

typedef unsigned long long ull;
__device__ __forceinline__ void f2_fma(ull& a, ull b, ull c) {
    asm("fma.rn.f32x2 %0, %1, %2, %0;" : "+l"(a) : "l"(b), "l"(c));
}
__device__ __forceinline__ float f2_sum(ull v) {
    float x, y; asm("mov.b64 {%0,%1}, %2;" : "=f"(x), "=f"(y) : "l"(v)); return x + y;
}

__device__ __forceinline__ void mma_bf16(float* c, const uint32_t* a, const uint32_t* b) {
    asm volatile(
        "mma.sync.aligned.m16n8k16.row.col.f32.bf16.bf16.f32 "
        "{%0,%1,%2,%3}, {%4,%5,%6,%7}, {%8,%9}, {%0,%1,%2,%3};"
        : "+f"(c[0]), "+f"(c[1]), "+f"(c[2]), "+f"(c[3])
        : "r"(a[0]), "r"(a[1]), "r"(a[2]), "r"(a[3]), "r"(b[0]), "r"(b[1]));
}

// ---- segment bounds ----
__global__ void k_init_rs(int N, int E) {
    int t = blockIdx.x * blockDim.x + threadIdx.x;
    if (t <= N) g_rs[t] = E;
}
__global__ void k_bounds(const int* __restrict__ center, int E) {
    int e = blockIdx.x * blockDim.x + threadIdx.x;
    if (e >= E) return;
    int c = center[e];
    int p = (e == 0) ? -1 : center[e - 1];
    for (int n = p + 1; n <= c; n++) g_rs[n] = e;
}

// ---- combined weights (bf16 hi/lo) ----
__global__ void k_m1(const float* __restrict__ WQ, const float* __restrict__ WK) {
    int k = blockIdx.x, o = threadIdx.x, h = o >> 7, j = o & 127;
    float s = 0.f;
#pragma unroll 8
    for (int d = 0; d < 32; d++)
        s += WQ[(size_t)(h * 32 + d) * 128 + k] * WK[(size_t)(h * 32 + d) * 128 + j];
    s *= 0.17677669529663687f;
    __nv_bfloat16 hi = __float2bfloat16(s);
    g_M1hi[o * 128 + k] = hi;
    g_M1lo[o * 128 + k] = __float2bfloat16(s - __bfloat162float(hi));
}
__global__ void k_m2(const float* __restrict__ WO, const float* __restrict__ WV) {
    int o = blockIdx.x, kk = threadIdx.x, h = kk >> 7, j = kk & 127;
    float s = 0.f;
#pragma unroll 8
    for (int d = 0; d < 32; d++)
        s += WO[(size_t)o * 128 + h * 32 + d] * WV[(size_t)(h * 32 + d) * 128 + j];
    __nv_bfloat16 hi = __float2bfloat16(s);
    g_M2hi[o * 512 + kk] = hi;
    g_M2lo[o * 512 + kk] = __float2bfloat16(s - __bfloat162float(hi));
}

#define PAD 136
#define SMEM_GEMM ((2 * 128 + 2 * 64) * PAD * 2)

__device__ __forceinline__ void store_hl(__nv_bfloat16* Ah, __nv_bfloat16* Al,
                                         int off, float2 v) {
    __nv_bfloat16 hx = __float2bfloat16(v.x), hy = __float2bfloat16(v.y);
    *(__nv_bfloat162*)(Ah + off) = __halves2bfloat162(hx, hy);
    __nv_bfloat16 lx = __float2bfloat16(v.x - __bfloat162float(hx));
    __nv_bfloat16 ly = __float2bfloat16(v.y - __bfloat162float(hy));
    *(__nv_bfloat162*)(Al + off) = __halves2bfloat162(lx, ly);
}

// ---- qk = hV @ M1  (M tile 128, N=512 in 8 chunks of 64, K=128) ----
__global__ __launch_bounds__(512, 2) void k_gemm_qk(const float* __restrict__ X, int N) {
    extern __shared__ char sm[];
    __nv_bfloat16* Ah = (__nv_bfloat16*)sm;
    __nv_bfloat16* Al = Ah + 128 * PAD;
    __nv_bfloat16* Bh = Al + 128 * PAD;
    __nv_bfloat16* Bl = Bh + 64 * PAD;
    int t = threadIdx.x, lane = t & 31, wid = t >> 5;
    int wr = wid >> 1, wc = wid & 1, g = lane >> 2, tig = lane & 3;
    int n0 = blockIdx.x * 128;

    for (int idx = t; idx < 128 * 64; idx += 512) {
        int r = idx >> 6, kp = (idx & 63) * 2;
        float2 v = (n0 + r < N) ? *(const float2*)(X + (size_t)(n0 + r) * 128 + kp)
                                : make_float2(0.f, 0.f);
        store_hl(Ah, Al, r * PAD + kp, v);
    }
    int ra = 16 * wr + g;
    for (int nc = 0; nc < 8; nc++) {
        if (nc) __syncthreads();
        for (int idx = t; idx < 64 * 16; idx += 512) {
            int r = idx >> 4, k8 = (idx & 15) * 8;
            *(uint4*)(Bh + r * PAD + k8) = *(const uint4*)(g_M1hi + (size_t)(nc * 64 + r) * 128 + k8);
            *(uint4*)(Bl + r * PAD + k8) = *(const uint4*)(g_M1lo + (size_t)(nc * 64 + r) * 128 + k8);
        }
        __syncthreads();
        float acc[4][4];
#pragma unroll
        for (int nt = 0; nt < 4; nt++)
#pragma unroll
            for (int c = 0; c < 4; c++) acc[nt][c] = 0.f;
#pragma unroll
        for (int ks = 0; ks < 8; ks++) {
            int k0 = 16 * ks + tig * 2;
            uint32_t ah[4], al[4];
            ah[0] = *(const uint32_t*)(Ah + ra * PAD + k0);
            ah[1] = *(const uint32_t*)(Ah + (ra + 8) * PAD + k0);
            ah[2] = *(const uint32_t*)(Ah + ra * PAD + k0 + 8);
            ah[3] = *(const uint32_t*)(Ah + (ra + 8) * PAD + k0 + 8);
            al[0] = *(const uint32_t*)(Al + ra * PAD + k0);
            al[1] = *(const uint32_t*)(Al + (ra + 8) * PAD + k0);
            al[2] = *(const uint32_t*)(Al + ra * PAD + k0 + 8);
            al[3] = *(const uint32_t*)(Al + (ra + 8) * PAD + k0 + 8);
#pragma unroll
            for (int nt = 0; nt < 4; nt++) {
                int nb = 32 * wc + 8 * nt + g;
                uint32_t bh[2], bl[2];
                bh[0] = *(const uint32_t*)(Bh + nb * PAD + k0);
                bh[1] = *(const uint32_t*)(Bh + nb * PAD + k0 + 8);
                bl[0] = *(const uint32_t*)(Bl + nb * PAD + k0);
                bl[1] = *(const uint32_t*)(Bl + nb * PAD + k0 + 8);
                mma_bf16(acc[nt], ah, bh);
                mma_bf16(acc[nt], ah, bl);
                mma_bf16(acc[nt], al, bh);
            }
        }
        int r0 = n0 + ra;
#pragma unroll
        for (int nt = 0; nt < 4; nt++) {
            int col = nc * 64 + 32 * wc + 8 * nt + tig * 2;
            if (r0 < N)
                *(float2*)(g_qk + (size_t)r0 * 512 + col) = make_float2(acc[nt][0], acc[nt][1]);
            if (r0 + 8 < N)
                *(float2*)(g_qk + (size_t)(r0 + 8) * 512 + col) = make_float2(acc[nt][2], acc[nt][3]);
        }
    }
}

// ---- out = agg @ M2  (M tile 128, N=128, K=512 in 4 chunks; B in 2 sub-chunks) ----
__global__ __launch_bounds__(512, 2) void k_gemm_out(float* __restrict__ OUT, int N) {
    extern __shared__ char sm[];
    __nv_bfloat16* Ah = (__nv_bfloat16*)sm;
    __nv_bfloat16* Al = Ah + 128 * PAD;
    __nv_bfloat16* Bh = Al + 128 * PAD;
    __nv_bfloat16* Bl = Bh + 64 * PAD;
    int t = threadIdx.x, lane = t & 31, wid = t >> 5;
    int wr = wid >> 1, wc = wid & 1, g = lane >> 2, tig = lane & 3;
    int n0 = blockIdx.x * 128;
    int ra = 16 * wr + g;

    float acc[8][4];
#pragma unroll
    for (int a = 0; a < 8; a++)
#pragma unroll
        for (int c = 0; c < 4; c++) acc[a][c] = 0.f;

    for (int kc = 0; kc < 4; kc++) {
        if (kc) __syncthreads();
        for (int idx = t; idx < 128 * 64; idx += 512) {
            int r = idx >> 6, kp = (idx & 63) * 2;
            float2 v = (n0 + r < N)
                ? *(const float2*)(g_agg + (size_t)(n0 + r) * 512 + kc * 128 + kp)
                : make_float2(0.f, 0.f);
            store_hl(Ah, Al, r * PAD + kp, v);
        }
        for (int sub = 0; sub < 2; sub++) {
            if (sub) __syncthreads();
            for (int idx = t; idx < 64 * 16; idx += 512) {
                int r = idx >> 4, k8 = (idx & 15) * 8;
                *(uint4*)(Bh + r * PAD + k8) =
                    *(const uint4*)(g_M2hi + (size_t)(sub * 64 + r) * 512 + kc * 128 + k8);
                *(uint4*)(Bl + r * PAD + k8) =
                    *(const uint4*)(g_M2lo + (size_t)(sub * 64 + r) * 512 + kc * 128 + k8);
            }
            __syncthreads();
#pragma unroll
            for (int ks = 0; ks < 8; ks++) {
                int k0 = 16 * ks + tig * 2;
                uint32_t ah[4], al[4];
                ah[0] = *(const uint32_t*)(Ah + ra * PAD + k0);
                ah[1] = *(const uint32_t*)(Ah + (ra + 8) * PAD + k0);
                ah[2] = *(const uint32_t*)(Ah + ra * PAD + k0 + 8);
                ah[3] = *(const uint32_t*)(Ah + (ra + 8) * PAD + k0 + 8);
                al[0] = *(const uint32_t*)(Al + ra * PAD + k0);
                al[1] = *(const uint32_t*)(Al + (ra + 8) * PAD + k0);
                al[2] = *(const uint32_t*)(Al + ra * PAD + k0 + 8);
                al[3] = *(const uint32_t*)(Al + (ra + 8) * PAD + k0 + 8);
#pragma unroll
                for (int nt = 0; nt < 4; nt++) {
                    int nb = 32 * wc + 8 * nt + g;
                    uint32_t bh[2], bl[2];
                    bh[0] = *(const uint32_t*)(Bh + nb * PAD + k0);
                    bh[1] = *(const uint32_t*)(Bh + nb * PAD + k0 + 8);
                    bl[0] = *(const uint32_t*)(Bl + nb * PAD + k0);
                    bl[1] = *(const uint32_t*)(Bl + nb * PAD + k0 + 8);
                    mma_bf16(acc[sub * 4 + nt], ah, bh);
                    mma_bf16(acc[sub * 4 + nt], ah, bl);
                    mma_bf16(acc[sub * 4 + nt], al, bh);
                }
            }
        }
    }
    int r0 = n0 + ra;
#pragma unroll
    for (int a = 0; a < 8; a++) {
        int col = (a >> 2) * 64 + 32 * wc + 8 * (a & 3) + tig * 2;
        if (r0 < N)
            *(float2*)(OUT + (size_t)r0 * 128 + col) = make_float2(acc[a][0], acc[a][1]);
        if (r0 + 8 < N)
            *(float2*)(OUT + (size_t)(r0 + 8) * 128 + col) = make_float2(acc[a][2], acc[a][3]);
    }
}

// ---- per-node single pass over h_E: SMEM online softmax + aggregation ----
// R14 structure (measured best), CH raised 40->44 (fast-path coverage ~98%).
#define CH 44
#define PADR 132
__global__ __launch_bounds__(256) void k_node(const float* __restrict__ hE, int N) {
    __shared__ alignas(16) float hE_s[CH * PADR];
    __shared__ alignas(16) float qk_s[4 * PADR];
    __shared__ alignas(16) float lgT[4 * 68];
    __shared__ alignas(16) float pT[4 * 68];
    __shared__ float m_s[4], s_s[4], sc_s[4];
    int t = threadIdx.x;
    int n = blockIdx.x;
    if (n >= N) return;
    int beg = g_rs[n], end = g_rs[n + 1];
    int w = t >> 5, l = t & 31;
    int hh2 = w & 3, jh = w >> 2, j1 = jh * 64 + l;

    if (end - beg <= CH) {
        // ---------- fast path ----------
        int cnt = end - beg;
        for (int idx = t; idx < 512; idx += 256) {
            int hh = idx >> 7, j = idx & 127;
            qk_s[hh * PADR + j] = g_qk[(size_t)n * 512 + idx];
        }
        for (int idx = t; idx < cnt * 32; idx += 256) {
            int r = idx >> 5, c4 = idx & 31;
            float4 v = *(const float4*)(hE + (size_t)(beg + r) * 128 + c4 * 4);
            *(float4*)(&hE_s[r * PADR + c4 * 4]) = v;
        }
        __syncthreads();
        {
            int e = t >> 2, hq = t & 3;
            if (e < cnt) {
                ull a0 = 0ull, a1 = 0ull;
                const float* qp = &qk_s[hq * PADR];
                const float* xp = &hE_s[e * PADR];
#pragma unroll
                for (int jj = 0; jj < 32; jj++) {
                    ulonglong2 q4 = *(const ulonglong2*)(qp + jj * 4);
                    ulonglong2 x4 = *(const ulonglong2*)(xp + jj * 4);
                    f2_fma(a0, q4.x, x4.x);
                    f2_fma(a1, q4.y, x4.y);
                }
                lgT[hq * 68 + e] = f2_sum(a0) + f2_sum(a1);
            }
        }
        __syncthreads();
        if (w < 4) {
            float v1 = (l < cnt) ? lgT[w * 68 + l] : NEG_BIG;
            float v2 = (l + 32 < cnt) ? lgT[w * 68 + l + 32] : NEG_BIG;
            float mx = fmaxf(v1, v2);
#pragma unroll
            for (int o = 16; o; o >>= 1) mx = fmaxf(mx, __shfl_xor_sync(0xffffffffu, mx, o));
            float p1 = (l < cnt) ? __expf(v1 - mx) : 0.f;
            float p2 = (l + 32 < cnt) ? __expf(v2 - mx) : 0.f;
            pT[w * 68 + l] = p1;
            pT[w * 68 + l + 32] = p2;
            float sv = p1 + p2;
#pragma unroll
            for (int o = 16; o; o >>= 1) sv += __shfl_xor_sync(0xffffffffu, sv, o);
            if (l == 0) s_s[w] = sv;
        }
        __syncthreads();
        {
            float aLo = 0.f, aHi = 0.f;
            const float* pp = &pT[hh2 * 68];
#pragma unroll 4
            for (int e = 0; e < cnt; e++) {
                float p = pp[e];
                aLo = fmaf(p, hE_s[e * PADR + j1], aLo);
                aHi = fmaf(p, hE_s[e * PADR + j1 + 32], aHi);
            }
            float inv = (cnt > 0) ? (1.0f / s_s[hh2]) : 0.f;
            g_agg[(size_t)n * 512 + hh2 * 128 + j1]      = aLo * inv;
            g_agg[(size_t)n * 512 + hh2 * 128 + j1 + 32] = aHi * inv;
        }
        return;
    }

    // ---------- general path: online softmax over chunks ----------
    for (int idx = t; idx < 512; idx += 256) {
        int hh = idx >> 7, j = idx & 127;
        qk_s[hh * PADR + j] = g_qk[(size_t)n * 512 + idx];
    }
    if (t < 4) { m_s[t] = NEG_BIG; s_s[t] = 0.f; }
    float accLo = 0.f, accHi = 0.f;
    __syncthreads();

    for (int cs = beg; cs < end; cs += CH) {
        int cnt = min(CH, end - cs);
        for (int idx = t; idx < cnt * 32; idx += 256) {
            int r = idx >> 5, c4 = idx & 31;
            float4 v = *(const float4*)(hE + (size_t)(cs + r) * 128 + c4 * 4);
            *(float4*)(&hE_s[r * PADR + c4 * 4]) = v;
        }
        __syncthreads();
        {
            int e = t >> 2, hq = t & 3;
            float lg = NEG_BIG;
            if (e < cnt) {
                ull a0 = 0ull, a1 = 0ull;
                const float* qp = &qk_s[hq * PADR];
                const float* xp = &hE_s[e * PADR];
#pragma unroll
                for (int jj = 0; jj < 32; jj++) {
                    ulonglong2 q4 = *(const ulonglong2*)(qp + jj * 4);
                    ulonglong2 x4 = *(const ulonglong2*)(xp + jj * 4);
                    f2_fma(a0, q4.x, x4.x);
                    f2_fma(a1, q4.y, x4.y);
                }
                lg = f2_sum(a0) + f2_sum(a1);
            }
            lgT[hq * 68 + e] = lg;
        }
        __syncthreads();
        if (t < 128) {
            int wh = t >> 5, l2 = t & 31;
            float v = fmaxf(lgT[wh * 68 + l2], lgT[wh * 68 + l2 + 32]);
#pragma unroll
            for (int o = 16; o; o >>= 1) v = fmaxf(v, __shfl_xor_sync(0xffffffffu, v, o));
            if (l2 == 0) {
                float old = m_s[wh], nm = fmaxf(old, v);
                sc_s[wh] = __expf(old - nm);
                m_s[wh] = nm;
            }
        }
        __syncthreads();
        {
            int e = t >> 2, hq = t & 3;
            pT[hq * 68 + e] = (e < cnt) ? __expf(lgT[hq * 68 + e] - m_s[hq]) : 0.f;
        }
        __syncthreads();
        if (t < 128) {
            int wh = t >> 5, l2 = t & 31;
            float v = pT[wh * 68 + l2] + pT[wh * 68 + l2 + 32];
#pragma unroll
            for (int o = 16; o; o >>= 1) v += __shfl_xor_sync(0xffffffffu, v, o);
            if (l2 == 0) s_s[wh] = s_s[wh] * sc_s[wh] + v;
        }
        {
            float sc = sc_s[hh2];
            accLo *= sc; accHi *= sc;
            const float* pp = &pT[hh2 * 68];
#pragma unroll 4
            for (int e = 0; e < cnt; e++) {
                float p = pp[e];
                accLo = fmaf(p, hE_s[e * PADR + j1], accLo);
                accHi = fmaf(p, hE_s[e * PADR + j1 + 32], accHi);
            }
        }
        __syncthreads();
    }
    float inv = (end > beg) ? (1.0f / s_s[hh2]) : 0.f;
    g_agg[(size_t)n * 512 + hh2 * 128 + j1]      = accLo * inv;
    g_agg[(size_t)n * 512 + hh2 * 128 + j1 + 32] = accHi * inv;
}

extern "C" void kernel_launch(void* const* d_in, const int* in_sizes, int n_in,
                              void* d_out, int out_size) {
    const float* hV = (const float*)d_in[0];
    const float* hE = (const float*)d_in[1];
    const int* center = (const int*)d_in[2];
    const float* WQ = (const float*)d_in[5];
    const float* WK = (const float*)d_in[6];
    const float* WV = (const float*)d_in[7];
    const float* WO = (const float*)d_in[8];
    float* out = (float*)d_out;
    int N = in_sizes[0] / 128;
    int E = in_sizes[1] / 128;
    int tiles = (N + 127) / 128;

    cudaFuncSetAttribute(k_gemm_qk, cudaFuncAttributeMaxDynamicSharedMemorySize, SMEM_GEMM);
    cudaFuncSetAttribute(k_gemm_out, cudaFuncAttributeMaxDynamicSharedMemorySize, SMEM_GEMM);

    k_init_rs<<<(N + 256) / 256, 256>>>(N, E);
    k_bounds<<<(E + 255) / 256, 256>>>(center, E);
    k_m1<<<128, 512>>>(WQ, WK);
    k_m2<<<128, 512>>>(WO, WV);
    k_gemm_qk<<<tiles, 512, SMEM_GEMM>>>(hV, N);    // qk = hV @ M1 (HMMA, 2 blocks/SM)
    k_node<<<N, 256>>>(hE, N);                      // softmax + aggregate
    k_gemm_out<<<tiles, 512, SMEM_GEMM>>>(out, N);  // out = agg @ M2 (HMMA, 2 blocks/SM)
}